// round 8
// baseline (speedup 1.0000x reference)
#include <cuda_runtime.h>
#include <math.h>

#define DDIM 512        // feature dim per row
#define GROUPS 128      // groups per row
#define GPB 64          // groups per block (row split across 2 blocks)
#define KCODES 1024
#define NTHREADS 256    // 8 warps
#define NWARPS 8
#define KCHUNK 128      // codes per warp chunk (8 warps x 128 = 1024 codes)
#define IDXMASK 0x3FFu
#define PACKMASK 0xFFFFFC00u

__device__ float g_partials[1024];
__device__ int   g_count = 0;

__global__ void __launch_bounds__(NTHREADS) vq_fused_kernel(
    const float* __restrict__ fb,
    const float* __restrict__ emb,
    float* __restrict__ out,
    int n_elems, int nblocks, int out_size)
{
    __shared__ float4 s_code[KCODES];     // 16 KB
    __shared__ float  s_nh[KCODES];       // -0.5*||e||^2, 4 KB
    __shared__ float  s_row[DDIM];        // 2 KB
    __shared__ float  s_m[GPB * NWARPS];  // packed chunk-partial best (m|idx), 2 KB
    __shared__ float  s_red[NWARPS];
    __shared__ float  s_scale[2];
    __shared__ bool   s_last;

    const int tid = threadIdx.x;
    const int row  = blockIdx.x >> 1;
    const int half = blockIdx.x & 1;      // which 64-group half of the row
    const float* x = fb + (size_t)row * DDIM;

    // ---- load codebook into smem, precompute -0.5*||e||^2 ----
    #pragma unroll
    for (int k = tid; k < KCODES; k += NTHREADS) {
        float4 e = reinterpret_cast<const float4*>(emb)[k];
        s_code[k] = e;
        s_nh[k] = -0.5f * (e.x*e.x + e.y*e.y + e.z*e.z + e.w*e.w);
    }

    // ---- load full row (norm needs all 512), sum of squares ----
    float ss = 0.0f;
    #pragma unroll
    for (int j = tid; j < DDIM; j += NTHREADS) {
        float v = x[j];
        s_row[j] = v;
        ss = fmaf(v, v, ss);
    }
    #pragma unroll
    for (int o = 16; o > 0; o >>= 1)
        ss += __shfl_xor_sync(0xffffffffu, ss, o);
    if ((tid & 31) == 0) s_red[tid >> 5] = ss;
    __syncthreads();

    if (tid == 0) {
        float tot = 0.0f;
        #pragma unroll
        for (int w = 0; w < NWARPS; w++) tot += s_red[w];
        float scale = sqrtf(tot);
        // FloatBiter (faithful fp32)
        float xc = fminf(fmaxf(scale + 1.0f, 1.0f), 16.0f);
        float lg = logf(xc) / 1.3862943611198906f;
        float s = 0.0f;
        #pragma unroll
        for (int i = 0; i < 8; i++) {
            float base = (float)(1 << i);
            int bit = ((int)floorf(lg * base)) & 1;
            s += (float)bit / base;
        }
        s_scale[0] = scale;
        s_scale[1] = powf(4.0f, s) - 1.0f;
    }
    __syncthreads();

    const float scale = s_scale[0];

    // ---- argmax of m_k = fn.e_k - 0.5||e_k||^2 over codes ----
    // 32 lanes x 2 groups = 64 groups; 8 warps each scan a 128-code chunk.
    // Index packed in low 10 mantissa bits -> running max is one FMNMX.
    const int gslot = tid & 31;
    const int kc = tid >> 5;              // warp id = chunk id (0..7)
    const int gl0 = gslot * 2;            // local group (0..63)
    const int gg0 = half * GPB + gl0;     // global group in row

    float xr[2][4];
    #pragma unroll
    for (int gg = 0; gg < 2; gg++)
        #pragma unroll
        for (int j = 0; j < 4; j++)
            xr[gg][j] = s_row[(gg0 + gg) * 4 + j] / scale;   // IEEE div == fn

    float best[2] = {-3e38f, -3e38f};
    const int kbeg = kc * KCHUNK;

    #pragma unroll 2
    for (int k4 = kbeg; k4 < kbeg + KCHUNK; k4 += 4) {
        float4 nh4 = *reinterpret_cast<const float4*>(&s_nh[k4]);  // LDS.128
        const float nh[4] = {nh4.x, nh4.y, nh4.z, nh4.w};
        #pragma unroll
        for (int u = 0; u < 4; u++) {
            const int k = k4 + u;
            float4 c = s_code[k];          // warp-uniform -> broadcast LDS.128
            #pragma unroll
            for (int gg = 0; gg < 2; gg++) {
                float m = fmaf(xr[gg][3], c.w,
                          fmaf(xr[gg][2], c.z,
                          fmaf(xr[gg][1], c.y,
                          fmaf(xr[gg][0], c.x, nh[u]))));
                float packed = __uint_as_float((__float_as_uint(m) & PACKMASK) | (unsigned)k);
                best[gg] = fmaxf(best[gg], packed);
            }
        }
    }
    #pragma unroll
    for (int gg = 0; gg < 2; gg++)
        s_m[(gl0 + gg) * NWARPS + kc] = best[gg];
    __syncthreads();

    // ---- combine chunk partials: one group per thread (first 64 threads) ----
    float l = 0.0f;
    if (tid < GPB) {
        const int gl = tid;
        const int g = half * GPB + gl;
        float bm = s_m[gl * NWARPS];
        #pragma unroll
        for (int c = 1; c < NWARPS; c++)
            bm = fmaxf(bm, s_m[gl * NWARPS + c]);
        const int bx = (int)(__float_as_uint(bm) & IDXMASK);

        float4 e = s_code[bx];
        const float sq = s_scale[1];
        reinterpret_cast<float4*>(out + (size_t)row * DDIM)[g] =
            make_float4(e.x * sq, e.y * sq, e.z * sq, e.w * sq);

        // loss: sum (fqn - fn)^2 (full-precision e, recomputed fn)
        float d0 = e.x - s_row[g * 4 + 0] / scale;
        float d1 = e.y - s_row[g * 4 + 1] / scale;
        float d2 = e.z - s_row[g * 4 + 2] / scale;
        float d3 = e.w - s_row[g * 4 + 3] / scale;
        l = d0*d0 + d1*d1 + d2*d2 + d3*d3;
    }
    // reduce l over first 2 warps (other threads contribute 0)
    #pragma unroll
    for (int o = 16; o > 0; o >>= 1)
        l += __shfl_xor_sync(0xffffffffu, l, o);
    __syncthreads();   // s_red reuse
    if ((tid & 31) == 0) s_red[tid >> 5] = l;
    __syncthreads();

    // ---- last-block fused loss reduction (deterministic fixed order) ----
    if (tid == 0) {
        g_partials[blockIdx.x] = s_red[0] + s_red[1];
        __threadfence();
        int prev = atomicAdd(&g_count, 1);
        s_last = (prev == nblocks - 1);
    }
    __syncthreads();

    if (s_last && tid < 128) {
        __threadfence();
        float v = 0.0f;
        #pragma unroll
        for (int i = 0; i < 8; i++)
            v += g_partials[tid + 128 * i];
        #pragma unroll
        for (int o = 16; o > 0; o >>= 1)
            v += __shfl_xor_sync(0xffffffffu, v, o);
        if ((tid & 31) == 0) s_red[tid >> 5] = v;
    }
    __syncthreads();
    if (s_last && tid == 0) {
        float loss = (s_red[0] + s_red[1] + s_red[2] + s_red[3]) / (float)n_elems;
        if (out_size >= n_elems + 1) out[n_elems] = loss;
        if (out_size >= n_elems + 2) out[n_elems + 1] = loss;
        g_count = 0;   // reset for next replay
    }
}

extern "C" void kernel_launch(void* const* d_in, const int* in_sizes, int n_in,
                              void* d_out, int out_size)
{
    const float* fb  = (const float*)d_in[0];
    const float* emb = (const float*)d_in[1];
    float* out = (float*)d_out;

    int n = in_sizes[0];       // 262144
    int rows = n / DDIM;       // 512
    int nblocks = rows * 2;    // 1024 (two group-halves per row)

    vq_fused_kernel<<<nblocks, NTHREADS>>>(fb, emb, out, n, nblocks, out_size);
}